// round 1
// baseline (speedup 1.0000x reference)
#include <cuda_runtime.h>
#include <cstdint>
#include <math.h>

#define BT 4096
#define HD 2048
#define VV 32000

// Scratch (allocation-free rule: static __device__ arrays)
__device__ float g_logits_s[(size_t)BT * VV];   // 512 MB
__device__ float g_logits_t[(size_t)BT * VV];   // 512 MB
__device__ float g_rowloss[BT];

// ---------------------------------------------------------------------------
// tf32 helpers
// ---------------------------------------------------------------------------
__device__ __forceinline__ float tf32_rna(float x) {
    uint32_t u;
    asm("cvt.rna.tf32.f32 %0, %1;" : "=r"(u) : "f"(x));
    return __uint_as_float(u);
}

__device__ __forceinline__ void mma_tf32(float c[4], const uint32_t a[4], const uint32_t b[2]) {
    asm volatile(
        "mma.sync.aligned.m16n8k8.row.col.f32.tf32.tf32.f32 "
        "{%0,%1,%2,%3}, {%4,%5,%6,%7}, {%8,%9}, {%0,%1,%2,%3};\n"
        : "+f"(c[0]), "+f"(c[1]), "+f"(c[2]), "+f"(c[3])
        : "r"(a[0]), "r"(a[1]), "r"(a[2]), "r"(a[3]), "r"(b[0]), "r"(b[1]));
}

// ---------------------------------------------------------------------------
// GEMM: Out[m, n] = sum_k X[m, k] * W[n, k]
// Tile: BM=128, BN=128, BK=16; 256 threads, warp grid 2(M) x 4(N), warp tile 64x32
// grid.x = 8000 linearized (m-tile fastest so W tiles are shared in L2),
// grid.z = 0: student, 1: teacher
// ---------------------------------------------------------------------------
#define SPITCH 132

__global__ __launch_bounds__(256, 2)
void gemm_tf32_kernel(const float* __restrict__ Xs, const float* __restrict__ Xt,
                      const float* __restrict__ Ws, const float* __restrict__ Wt) {
    __shared__ float As[16][SPITCH];
    __shared__ float Bs[16][SPITCH];

    const float* X = blockIdx.z ? Xt : Xs;
    const float* W = blockIdx.z ? Wt : Ws;
    float* Out = blockIdx.z ? g_logits_t : g_logits_s;

    const int bid = blockIdx.x;
    const int m0 = (bid & 31) << 7;     // 32 m-tiles, fastest-varying
    const int n0 = (bid >> 5) << 7;     // 250 n-tiles

    const int tid = threadIdx.x;
    const int lane = tid & 31;
    const int warp = tid >> 5;
    const int g = lane >> 2;          // groupID (lane/4)
    const int tig = lane & 3;         // thread-in-group
    const int warpM = (warp & 1) * 64;
    const int warpN = (warp >> 1) * 32;

    float c[4][4][4];
#pragma unroll
    for (int mt = 0; mt < 4; ++mt)
#pragma unroll
        for (int nt = 0; nt < 4; ++nt)
#pragma unroll
            for (int i = 0; i < 4; ++i) c[mt][nt][i] = 0.0f;

    for (int kt = 0; kt < HD; kt += 16) {
#pragma unroll
        for (int it = 0; it < 2; ++it) {
            const int idx = tid + it * 256;      // 0..511
            const int mm = idx >> 2;             // 0..127
            const int k4 = (idx & 3) << 2;       // 0,4,8,12
            float4 va = *reinterpret_cast<const float4*>(&X[(size_t)(m0 + mm) * HD + kt + k4]);
            float4 vb = *reinterpret_cast<const float4*>(&W[(size_t)(n0 + mm) * HD + kt + k4]);
            As[k4 + 0][mm] = tf32_rna(va.x);
            As[k4 + 1][mm] = tf32_rna(va.y);
            As[k4 + 2][mm] = tf32_rna(va.z);
            As[k4 + 3][mm] = tf32_rna(va.w);
            Bs[k4 + 0][mm] = tf32_rna(vb.x);
            Bs[k4 + 1][mm] = tf32_rna(vb.y);
            Bs[k4 + 2][mm] = tf32_rna(vb.z);
            Bs[k4 + 3][mm] = tf32_rna(vb.w);
        }
        __syncthreads();

#pragma unroll
        for (int kc = 0; kc < 16; kc += 8) {
            uint32_t a[4][4];
            uint32_t b[4][2];
#pragma unroll
            for (int mt = 0; mt < 4; ++mt) {
                const int r = warpM + mt * 16 + g;
                a[mt][0] = __float_as_uint(As[kc + tig][r]);
                a[mt][1] = __float_as_uint(As[kc + tig][r + 8]);
                a[mt][2] = __float_as_uint(As[kc + tig + 4][r]);
                a[mt][3] = __float_as_uint(As[kc + tig + 4][r + 8]);
            }
#pragma unroll
            for (int nt = 0; nt < 4; ++nt) {
                const int cn = warpN + nt * 8 + g;
                b[nt][0] = __float_as_uint(Bs[kc + tig][cn]);
                b[nt][1] = __float_as_uint(Bs[kc + tig + 4][cn]);
            }
#pragma unroll
            for (int mt = 0; mt < 4; ++mt)
#pragma unroll
                for (int nt = 0; nt < 4; ++nt)
                    mma_tf32(c[mt][nt], a[mt], b[nt]);
        }
        __syncthreads();
    }

    // epilogue: c0,c1 -> (row, 2*tig..2*tig+1); c2,c3 -> (row+8, same cols)
#pragma unroll
    for (int mt = 0; mt < 4; ++mt) {
#pragma unroll
        for (int nt = 0; nt < 4; ++nt) {
            const int r = m0 + warpM + mt * 16 + g;
            const int cn = n0 + warpN + nt * 8 + tig * 2;
            float2 v01 = make_float2(c[mt][nt][0], c[mt][nt][1]);
            float2 v23 = make_float2(c[mt][nt][2], c[mt][nt][3]);
            *reinterpret_cast<float2*>(&Out[(size_t)r * VV + cn]) = v01;
            *reinterpret_cast<float2*>(&Out[(size_t)(r + 8) * VV + cn]) = v23;
        }
    }
}

// ---------------------------------------------------------------------------
// Block reductions (deterministic, fixed order)
// ---------------------------------------------------------------------------
__device__ __forceinline__ float warpReduceSum(float v) {
#pragma unroll
    for (int o = 16; o > 0; o >>= 1) v += __shfl_xor_sync(0xffffffffu, v, o);
    return v;
}
__device__ __forceinline__ float warpReduceMax(float v) {
#pragma unroll
    for (int o = 16; o > 0; o >>= 1) v = fmaxf(v, __shfl_xor_sync(0xffffffffu, v, o));
    return v;
}
__device__ __forceinline__ float blockReduceSum(float v, float* sm) {
    v = warpReduceSum(v);
    __syncthreads();
    if ((threadIdx.x & 31) == 0) sm[threadIdx.x >> 5] = v;
    __syncthreads();
    float r = sm[0];
#pragma unroll
    for (int i = 1; i < 8; ++i) r += sm[i];
    return r;
}
__device__ __forceinline__ float blockReduceMax(float v, float* sm) {
    v = warpReduceMax(v);
    __syncthreads();
    if ((threadIdx.x & 31) == 0) sm[threadIdx.x >> 5] = v;
    __syncthreads();
    float r = sm[0];
#pragma unroll
    for (int i = 1; i < 8; ++i) r = fmaxf(r, sm[i]);
    return r;
}

// ---------------------------------------------------------------------------
// Per-row JSD (beta = 0.5, T = 1): 3 passes over the row; passes 2 and 3 hit L2
// ---------------------------------------------------------------------------
__global__ __launch_bounds__(256)
void jsd_kernel() {
    __shared__ float sm[8];
    const int row = blockIdx.x;
    const int tid = threadIdx.x;
    const float* s = g_logits_s + (size_t)row * VV;
    const float* t = g_logits_t + (size_t)row * VV;

    // pass 1: row maxima
    float ms = -1e30f, mt = -1e30f;
    for (int j = tid; j < VV; j += 256) {
        ms = fmaxf(ms, s[j]);
        mt = fmaxf(mt, t[j]);
    }
    ms = blockReduceMax(ms, sm);
    mt = blockReduceMax(mt, sm);

    // pass 2: sum of exponentials
    float ss = 0.0f, st = 0.0f;
    for (int j = tid; j < VV; j += 256) {
        ss += __expf(s[j] - ms);
        st += __expf(t[j] - mt);
    }
    ss = blockReduceSum(ss, sm);
    st = blockReduceSum(st, sm);
    const float lse_s = ms + __logf(ss);
    const float lse_t = mt + __logf(st);

    // pass 3: JSD terms
    float acc = 0.0f;
    for (int j = tid; j < VV; j += 256) {
        const float lq = s[j] - lse_s;   // student log-prob
        const float lp = t[j] - lse_t;   // teacher log-prob
        const float q = __expf(lq);
        const float p = __expf(lp);
        const float m = 0.5f * (p + q);
        const float lm = __logf(fmaxf(m, 1e-30f));
        acc += 0.5f * (p * (lp - lm) + q * (lq - lm));
    }
    acc = blockReduceSum(acc, sm);
    if (tid == 0) g_rowloss[row] = acc;
}

__global__ __launch_bounds__(256)
void finalize_kernel(float* out) {
    __shared__ float sm[8];
    float v = 0.0f;
    for (int i = threadIdx.x; i < BT; i += 256) v += g_rowloss[i];
    v = blockReduceSum(v, sm);
    if (threadIdx.x == 0) out[0] = v * (1.0f / (float)BT);
}

// ---------------------------------------------------------------------------
// Launch
// ---------------------------------------------------------------------------
extern "C" void kernel_launch(void* const* d_in, const int* in_sizes, int n_in,
                              void* d_out, int out_size) {
    const float* xs = (const float*)d_in[0];   // student_input [BT, H]
    const float* xt = (const float*)d_in[1];   // teacher_input [BT, H]
    const float* ws = (const float*)d_in[2];   // w_student [V, H]
    const float* wt = (const float*)d_in[3];   // w_teacher [V, H]

    dim3 grid((BT / 128) * (VV / 128), 1, 2);  // 8000 x 1 x 2
    gemm_tf32_kernel<<<grid, 256>>>(xs, xt, ws, wt);
    jsd_kernel<<<BT, 256>>>();
    finalize_kernel<<<1, 256>>>((float*)d_out);
}

// round 4
// speedup vs baseline: 3.8685x; 3.8685x over previous
#include <cuda_runtime.h>
#include <cuda_bf16.h>
#include <cstdint>
#include <math.h>

#define BT 4096
#define HD 2048
#define VV 32000

#define BM 128
#define BN 128
#define BK 64                       // bf16 elements per k-stage
#define STAGES 3
#define NITER (HD / BK)             // 32
#define TILE_BYTES (128 * 128)      // 16 KB per operand tile (128 rows x 128 B)
#define STAGE_BYTES (2 * TILE_BYTES)
#define SMEM_TOTAL (STAGES * STAGE_BYTES)   // 96 KB

#define M_TILES (BT / BM)           // 32
#define N_TILES (VV / BN)           // 250

// ---------------------------------------------------------------------------
// Scratch (static __device__; referenced ONLY from device code)
// ---------------------------------------------------------------------------
__device__ float g_logits_s[(size_t)BT * VV];   // 512 MB
__device__ float g_logits_t[(size_t)BT * VV];   // 512 MB
__device__ float g_rowloss[BT];
__device__ __align__(16) __nv_bfloat16 g_Xb[(size_t)2 * BT * HD];   // 33.5 MB
__device__ __align__(16) __nv_bfloat16 g_Wb[(size_t)2 * VV * HD];   // 262 MB

// ---------------------------------------------------------------------------
// PTX helpers (baseline ISA only: cp.async, ldmatrix, mma.sync)
// ---------------------------------------------------------------------------
__device__ __forceinline__ uint32_t smem_u32(const void* p) {
    uint32_t a;
    asm("{ .reg .u64 t; cvta.to.shared.u64 t, %1; cvt.u32.u64 %0, t; }" : "=r"(a) : "l"(p));
    return a;
}

#define CP_ASYNC16(dst, src) \
    asm volatile("cp.async.cg.shared.global [%0], [%1], 16;" :: "r"(dst), "l"(src))
#define CP_COMMIT() asm volatile("cp.async.commit_group;" ::: "memory")
#define CP_WAIT(n)  asm volatile("cp.async.wait_group %0;" :: "n"(n) : "memory")

__device__ __forceinline__ void ldsm_x4(uint32_t& r0, uint32_t& r1, uint32_t& r2, uint32_t& r3,
                                        uint32_t addr) {
    asm volatile("ldmatrix.sync.aligned.m8n8.x4.shared.b16 {%0,%1,%2,%3}, [%4];"
                 : "=r"(r0), "=r"(r1), "=r"(r2), "=r"(r3) : "r"(addr));
}

__device__ __forceinline__ void mma_bf16(float c[4], const uint32_t a[4], const uint32_t b[2]) {
    asm volatile(
        "mma.sync.aligned.m16n8k16.row.col.f32.bf16.bf16.f32 "
        "{%0,%1,%2,%3}, {%4,%5,%6,%7}, {%8,%9}, {%0,%1,%2,%3};\n"
        : "+f"(c[0]), "+f"(c[1]), "+f"(c[2]), "+f"(c[3])
        : "r"(a[0]), "r"(a[1]), "r"(a[2]), "r"(a[3]), "r"(b[0]), "r"(b[1]));
}

// SW128 swizzle inside a 128-row x 128-byte tile: (row, kc16) -> byte offset, kc16 in 0..7
__device__ __forceinline__ uint32_t tile_off(int row, int kc) {
    return (uint32_t)(row * 128 + ((kc ^ (row & 7)) << 4));
}

// ---------------------------------------------------------------------------
// fp32 -> bf16 conversion. dst selected INSIDE device code (device symbols
// must never be passed from host).
// ---------------------------------------------------------------------------
__device__ __forceinline__ uint32_t pack2bf(float a, float b) {
    __nv_bfloat162 h = __floats2bfloat162_rn(a, b);
    return *reinterpret_cast<uint32_t*>(&h);
}

__global__ __launch_bounds__(256) void conv_kernel(const float* __restrict__ src0,
                                                   const float* __restrict__ src1,
                                                   int isW) {
    const size_t n_per_model = isW ? (size_t)VV * HD : (size_t)BT * HD;
    __nv_bfloat16* dst = (isW ? g_Wb : g_Xb) + blockIdx.y * n_per_model;
    const float* src = blockIdx.y ? src1 : src0;
    const size_t idx = ((size_t)blockIdx.x * 256 + threadIdx.x) * 8;
    float4 f0 = *reinterpret_cast<const float4*>(src + idx);
    float4 f1 = *reinterpret_cast<const float4*>(src + idx + 4);
    uint4 u;
    u.x = pack2bf(f0.x, f0.y);  u.y = pack2bf(f0.z, f0.w);
    u.z = pack2bf(f1.x, f1.y);  u.w = pack2bf(f1.z, f1.w);
    *reinterpret_cast<uint4*>(dst + idx) = u;
}

// ---------------------------------------------------------------------------
// GEMM: logits[m, n] = sum_k Xb[m, k] * Wb[n, k]
// 256 threads = 8 warps in 2(M) x 4(N); warp tile 64x32 via m16n8k16.
// grid.x linearized m-fastest (32 CTAs share each W tile in L2), grid.z = model
// ---------------------------------------------------------------------------
__global__ __launch_bounds__(256, 2) void gemm_bf16_kernel() {
    extern __shared__ __align__(1024) uint8_t smem[];
    const uint32_t sbase = smem_u32(smem);

    const int bid = blockIdx.x;
    const int m0 = (bid & 31) << 7;
    const int n0 = (bid >> 5) << 7;
    const int model = blockIdx.z;

    const __nv_bfloat16* X = g_Xb + (size_t)model * BT * HD;
    const __nv_bfloat16* W = g_Wb + (size_t)model * VV * HD;
    float* Out = model ? g_logits_t : g_logits_s;

    const int tid = threadIdx.x;
    const int lane = tid & 31;
    const int warp = tid >> 5;
    const int warpM = (warp & 1) * 64;
    const int warpN = (warp >> 1) * 32;

    // cp.async mapping: 1024 16-B chunks per tile, 4 per thread
    const int ld_row = tid >> 3;          // base row (stride 32 over 4 iters)
    const int ld_kc = tid & 7;

    float acc[4][4][4];
#pragma unroll
    for (int mt = 0; mt < 4; ++mt)
#pragma unroll
        for (int nt = 0; nt < 4; ++nt)
#pragma unroll
            for (int i = 0; i < 4; ++i) acc[mt][nt][i] = 0.0f;

    auto load_stage = [&](int it) {
        const int slot = it % STAGES;
        const uint32_t sA = sbase + slot * STAGE_BYTES;
        const uint32_t sB = sA + TILE_BYTES;
        const int kt = it * BK;
#pragma unroll
        for (int i = 0; i < 4; ++i) {
            const int row = ld_row + i * 32;
            const uint32_t off = tile_off(row, ld_kc);
            CP_ASYNC16(sA + off, X + (size_t)(m0 + row) * HD + kt + ld_kc * 8);
            CP_ASYNC16(sB + off, W + (size_t)(n0 + row) * HD + kt + ld_kc * 8);
        }
        CP_COMMIT();
    };

    load_stage(0);
    load_stage(1);

    // ldmatrix per-lane address components
    const int a_r = lane & 15;            // A: row within 16
    const int a_k = lane >> 4;            // A: 0/1 -> k-chunk select
    const int b_n = (lane & 7) + ((lane >> 4) & 1) * 8;  // B: n-row
    const int b_k = (lane >> 3) & 1;                      // B: k-chunk select

    for (int it = 0; it < NITER; ++it) {
        CP_WAIT(1);
        __syncthreads();
        if (it + 2 < NITER) load_stage(it + 2);
        else CP_COMMIT();   // empty group: keeps CP_WAIT(1) draining the real tail

        const int slot = it % STAGES;
        const uint32_t sA = sbase + slot * STAGE_BYTES;
        const uint32_t sB = sA + TILE_BYTES;

#pragma unroll
        for (int ks = 0; ks < 4; ++ks) {
            uint32_t a[4][4];
            uint32_t b[4][2];
#pragma unroll
            for (int mt = 0; mt < 4; ++mt) {
                const int row = warpM + mt * 16 + a_r;
                ldsm_x4(a[mt][0], a[mt][1], a[mt][2], a[mt][3],
                        sA + tile_off(row, ks * 2 + a_k));
            }
#pragma unroll
            for (int nh = 0; nh < 2; ++nh) {
                const int row = warpN + nh * 16 + b_n;
                uint32_t r0, r1, r2, r3;
                ldsm_x4(r0, r1, r2, r3, sB + tile_off(row, ks * 2 + b_k));
                b[nh * 2 + 0][0] = r0;  b[nh * 2 + 0][1] = r1;
                b[nh * 2 + 1][0] = r2;  b[nh * 2 + 1][1] = r3;
            }
#pragma unroll
            for (int mt = 0; mt < 4; ++mt)
#pragma unroll
                for (int nt = 0; nt < 4; ++nt)
                    mma_bf16(acc[mt][nt], a[mt], b[nt]);
        }
    }

    const int g = lane >> 2;
    const int tig = lane & 3;
#pragma unroll
    for (int mt = 0; mt < 4; ++mt) {
#pragma unroll
        for (int nt = 0; nt < 4; ++nt) {
            const int r = m0 + warpM + mt * 16 + g;
            const int cn = n0 + warpN + nt * 8 + tig * 2;
            *reinterpret_cast<float2*>(&Out[(size_t)r * VV + cn]) =
                make_float2(acc[mt][nt][0], acc[mt][nt][1]);
            *reinterpret_cast<float2*>(&Out[(size_t)(r + 8) * VV + cn]) =
                make_float2(acc[mt][nt][2], acc[mt][nt][3]);
        }
    }
}

// ---------------------------------------------------------------------------
// Reductions (deterministic)
// ---------------------------------------------------------------------------
__device__ __forceinline__ float warpReduceSum(float v) {
#pragma unroll
    for (int o = 16; o > 0; o >>= 1) v += __shfl_xor_sync(0xffffffffu, v, o);
    return v;
}
__device__ __forceinline__ float warpReduceMax(float v) {
#pragma unroll
    for (int o = 16; o > 0; o >>= 1) v = fmaxf(v, __shfl_xor_sync(0xffffffffu, v, o));
    return v;
}
__device__ __forceinline__ float blockReduceSum(float v, float* sp) {
    v = warpReduceSum(v);
    __syncthreads();
    if ((threadIdx.x & 31) == 0) sp[threadIdx.x >> 5] = v;
    __syncthreads();
    float r = sp[0];
#pragma unroll
    for (int i = 1; i < 8; ++i) r += sp[i];
    return r;
}
__device__ __forceinline__ float blockReduceMax(float v, float* sp) {
    v = warpReduceMax(v);
    __syncthreads();
    if ((threadIdx.x & 31) == 0) sp[threadIdx.x >> 5] = v;
    __syncthreads();
    float r = sp[0];
#pragma unroll
    for (int i = 1; i < 8; ++i) r = fmaxf(r, sp[i]);
    return r;
}

// ---------------------------------------------------------------------------
// Per-row JSD (beta = 0.5, T = 1), 2 passes: online logsumexp then JSD terms
// ---------------------------------------------------------------------------
__global__ __launch_bounds__(256) void jsd_kernel() {
    __shared__ float sp[8];
    const int row = blockIdx.x;
    const int tid = threadIdx.x;
    const float* s = g_logits_s + (size_t)row * VV;
    const float* t = g_logits_t + (size_t)row * VV;

    float ms = -1e30f, ss = 0.0f, mt = -1e30f, st = 0.0f;
    for (int j = tid; j < VV; j += 256) {
        const float vs = s[j];
        if (vs > ms) { ss = ss * __expf(ms - vs) + 1.0f; ms = vs; }
        else         { ss += __expf(vs - ms); }
        const float vt = t[j];
        if (vt > mt) { st = st * __expf(mt - vt) + 1.0f; mt = vt; }
        else         { st += __expf(vt - mt); }
    }
    const float Ms = blockReduceMax(ms, sp);
    const float Mt = blockReduceMax(mt, sp);
    ss *= __expf(ms - Ms);
    st *= __expf(mt - Mt);
    const float Ss = blockReduceSum(ss, sp);
    const float St = blockReduceSum(st, sp);
    const float lse_s = Ms + __logf(Ss);
    const float lse_t = Mt + __logf(St);

    float acc = 0.0f;
    for (int j = tid; j < VV; j += 256) {
        const float lq = s[j] - lse_s;
        const float lp = t[j] - lse_t;
        const float q = __expf(lq);
        const float p = __expf(lp);
        const float m = 0.5f * (p + q);
        const float lm = __logf(fmaxf(m, 1e-30f));
        acc += 0.5f * (p * (lp - lm) + q * (lq - lm));
    }
    acc = blockReduceSum(acc, sp);
    if (tid == 0) g_rowloss[row] = acc;
}

__global__ __launch_bounds__(256) void finalize_kernel(float* out) {
    __shared__ float sp[8];
    float v = 0.0f;
    for (int i = threadIdx.x; i < BT; i += 256) v += g_rowloss[i];
    v = blockReduceSum(v, sp);
    if (threadIdx.x == 0) out[0] = v * (1.0f / (float)BT);
}

// ---------------------------------------------------------------------------
// Launch
// ---------------------------------------------------------------------------
extern "C" void kernel_launch(void* const* d_in, const int* in_sizes, int n_in,
                              void* d_out, int out_size) {
    const float* xs = (const float*)d_in[0];
    const float* xt = (const float*)d_in[1];
    const float* ws = (const float*)d_in[2];
    const float* wt = (const float*)d_in[3];

    conv_kernel<<<dim3((BT * HD) / (256 * 8), 2), 256>>>(xs, xt, 0);
    conv_kernel<<<dim3((VV * HD) / (256 * 8), 2), 256>>>(ws, wt, 1);

    cudaFuncSetAttribute(gemm_bf16_kernel,
                         cudaFuncAttributeMaxDynamicSharedMemorySize, SMEM_TOTAL);
    gemm_bf16_kernel<<<dim3(M_TILES * N_TILES, 1, 2), 256, SMEM_TOTAL>>>();

    jsd_kernel<<<BT, 256>>>();
    finalize_kernel<<<1, 256>>>((float*)d_out);
}

// round 5
// speedup vs baseline: 3.9317x; 1.0163x over previous
#include <cuda_runtime.h>
#include <cuda_bf16.h>
#include <cuda_fp16.h>
#include <cstdint>
#include <math.h>

#define BT 4096
#define HD 2048
#define VV 32000

#define BM 128
#define BN 256
#define BK 64                       // bf16 elements per k-stage
#define STAGES 3
#define NITER (HD / BK)             // 32
#define A_BYTES (BM * 128)          // 16 KB
#define B_BYTES (BN * 128)          // 32 KB
#define STAGE_BYTES (A_BYTES + B_BYTES)
#define SMEM_TOTAL (STAGES * STAGE_BYTES)   // 144 KB

#define M_TILES (BT / BM)           // 32
#define N_TILES (VV / BN)           // 125

// ---------------------------------------------------------------------------
// Scratch (static __device__; referenced ONLY from device code)
// ---------------------------------------------------------------------------
__device__ __half g_logits_s[(size_t)BT * VV];   // 256 MB
__device__ __half g_logits_t[(size_t)BT * VV];   // 256 MB
__device__ float g_rowloss[BT];
__device__ __align__(16) __nv_bfloat16 g_Xb[(size_t)2 * BT * HD];   // 33.5 MB
__device__ __align__(16) __nv_bfloat16 g_Wb[(size_t)2 * VV * HD];   // 262 MB

// ---------------------------------------------------------------------------
// PTX helpers (baseline ISA only: cp.async, ldmatrix, mma.sync)
// ---------------------------------------------------------------------------
__device__ __forceinline__ uint32_t smem_u32(const void* p) {
    uint32_t a;
    asm("{ .reg .u64 t; cvta.to.shared.u64 t, %1; cvt.u32.u64 %0, t; }" : "=r"(a) : "l"(p));
    return a;
}

#define CP_ASYNC16(dst, src) \
    asm volatile("cp.async.cg.shared.global [%0], [%1], 16;" :: "r"(dst), "l"(src))
#define CP_COMMIT() asm volatile("cp.async.commit_group;" ::: "memory")
#define CP_WAIT(n)  asm volatile("cp.async.wait_group %0;" :: "n"(n) : "memory")

__device__ __forceinline__ void ldsm_x4(uint32_t& r0, uint32_t& r1, uint32_t& r2, uint32_t& r3,
                                        uint32_t addr) {
    asm volatile("ldmatrix.sync.aligned.m8n8.x4.shared.b16 {%0,%1,%2,%3}, [%4];"
                 : "=r"(r0), "=r"(r1), "=r"(r2), "=r"(r3) : "r"(addr));
}

__device__ __forceinline__ void mma_bf16(float c[4], const uint32_t a[4], const uint32_t b[2]) {
    asm volatile(
        "mma.sync.aligned.m16n8k16.row.col.f32.bf16.bf16.f32 "
        "{%0,%1,%2,%3}, {%4,%5,%6,%7}, {%8,%9}, {%0,%1,%2,%3};\n"
        : "+f"(c[0]), "+f"(c[1]), "+f"(c[2]), "+f"(c[3])
        : "r"(a[0]), "r"(a[1]), "r"(a[2]), "r"(a[3]), "r"(b[0]), "r"(b[1]));
}

// SW128 swizzle inside a row-major (row x 128 B) tile; kc16 in 0..7
__device__ __forceinline__ uint32_t tile_off(int row, int kc) {
    return (uint32_t)(row * 128 + ((kc ^ (row & 7)) << 4));
}

// ---------------------------------------------------------------------------
// fp32 -> bf16 conversion. dst chosen inside device code.
// ---------------------------------------------------------------------------
__device__ __forceinline__ uint32_t pack2bf(float a, float b) {
    __nv_bfloat162 h = __floats2bfloat162_rn(a, b);
    return *reinterpret_cast<uint32_t*>(&h);
}

__global__ __launch_bounds__(256) void conv_kernel(const float* __restrict__ src0,
                                                   const float* __restrict__ src1,
                                                   int isW) {
    const size_t n_per_model = isW ? (size_t)VV * HD : (size_t)BT * HD;
    __nv_bfloat16* dst = (isW ? g_Wb : g_Xb) + blockIdx.y * n_per_model;
    const float* src = blockIdx.y ? src1 : src0;
    const size_t idx = ((size_t)blockIdx.x * 256 + threadIdx.x) * 8;
    float4 f0 = *reinterpret_cast<const float4*>(src + idx);
    float4 f1 = *reinterpret_cast<const float4*>(src + idx + 4);
    uint4 u;
    u.x = pack2bf(f0.x, f0.y);  u.y = pack2bf(f0.z, f0.w);
    u.z = pack2bf(f1.x, f1.y);  u.w = pack2bf(f1.z, f1.w);
    *reinterpret_cast<uint4*>(dst + idx) = u;
}

// ---------------------------------------------------------------------------
// GEMM: logits[m, n] = sum_k Xb[m, k] * Wb[n, k]  -> fp16 logits
// CTA tile 128x256, 8 warps in 2(M) x 4(N), warp tile 64x64 (m16n8k16)
// grid.x m-fastest so 32 CTAs share each W tile in L2; grid.z = model
// ---------------------------------------------------------------------------
__global__ __launch_bounds__(256, 1) void gemm_bf16_kernel() {
    extern __shared__ __align__(1024) uint8_t smem[];
    const uint32_t sbase = smem_u32(smem);

    const int bid = blockIdx.x;
    const int m0 = (bid & 31) << 7;       // 32 m-tiles fastest
    const int n0 = (bid >> 5) << 8;       // 125 n-tiles of 256
    const int model = blockIdx.z;

    const __nv_bfloat16* X = g_Xb + (size_t)model * BT * HD;
    const __nv_bfloat16* W = g_Wb + (size_t)model * VV * HD;
    __half* Out = model ? g_logits_t : g_logits_s;

    const int tid = threadIdx.x;
    const int lane = tid & 31;
    const int warp = tid >> 5;
    const int warpM = (warp & 1) * 64;
    const int warpN = (warp >> 1) * 64;

    // cp.async mapping: rows tid>>3 (+32*i), kc = tid&7
    const int ld_row = tid >> 3;
    const int ld_kc = tid & 7;

    float acc[4][8][4];
#pragma unroll
    for (int mt = 0; mt < 4; ++mt)
#pragma unroll
        for (int nt = 0; nt < 8; ++nt)
#pragma unroll
            for (int i = 0; i < 4; ++i) acc[mt][nt][i] = 0.0f;

    auto load_stage = [&](int it) {
        const int slot = it % STAGES;
        const uint32_t sA = sbase + slot * STAGE_BYTES;
        const uint32_t sB = sA + A_BYTES;
        const int kt = it * BK;
#pragma unroll
        for (int i = 0; i < 4; ++i) {
            const int row = ld_row + i * 32;
            CP_ASYNC16(sA + tile_off(row, ld_kc), X + (size_t)(m0 + row) * HD + kt + ld_kc * 8);
        }
#pragma unroll
        for (int i = 0; i < 8; ++i) {
            const int row = ld_row + i * 32;
            CP_ASYNC16(sB + tile_off(row, ld_kc), W + (size_t)(n0 + row) * HD + kt + ld_kc * 8);
        }
        CP_COMMIT();
    };

    load_stage(0);
    load_stage(1);

    // ldmatrix per-lane address components
    const int a_r = lane & 15;                            // A: row within 16
    const int a_k = lane >> 4;                            // A: k-chunk select
    const int b_n = (lane & 7) + ((lane >> 4) & 1) * 8;   // B: n-row within 16
    const int b_k = (lane >> 3) & 1;                      // B: k-chunk select

    for (int it = 0; it < NITER; ++it) {
        CP_WAIT(1);
        __syncthreads();
        if (it + 2 < NITER) load_stage(it + 2);
        else CP_COMMIT();   // empty group keeps CP_WAIT(1) draining the real tail

        const int slot = it % STAGES;
        const uint32_t sA = sbase + slot * STAGE_BYTES;
        const uint32_t sB = sA + A_BYTES;

#pragma unroll
        for (int ks = 0; ks < 4; ++ks) {
            uint32_t a[4][4];
            uint32_t b[8][2];
#pragma unroll
            for (int mt = 0; mt < 4; ++mt) {
                const int row = warpM + mt * 16 + a_r;
                ldsm_x4(a[mt][0], a[mt][1], a[mt][2], a[mt][3],
                        sA + tile_off(row, ks * 2 + a_k));
            }
#pragma unroll
            for (int nh = 0; nh < 4; ++nh) {
                const int row = warpN + nh * 16 + b_n;
                uint32_t r0, r1, r2, r3;
                ldsm_x4(r0, r1, r2, r3, sB + tile_off(row, ks * 2 + b_k));
                b[nh * 2 + 0][0] = r0;  b[nh * 2 + 0][1] = r1;
                b[nh * 2 + 1][0] = r2;  b[nh * 2 + 1][1] = r3;
            }
#pragma unroll
            for (int mt = 0; mt < 4; ++mt)
#pragma unroll
                for (int nt = 0; nt < 8; ++nt)
                    mma_bf16(acc[mt][nt], a[mt], b[nt]);
        }
    }

    const int g = lane >> 2;
    const int tig = lane & 3;
#pragma unroll
    for (int mt = 0; mt < 4; ++mt) {
#pragma unroll
        for (int nt = 0; nt < 8; ++nt) {
            const int r = m0 + warpM + mt * 16 + g;
            const int cn = n0 + warpN + nt * 8 + tig * 2;
            __half2 h01 = __floats2half2_rn(acc[mt][nt][0], acc[mt][nt][1]);
            __half2 h23 = __floats2half2_rn(acc[mt][nt][2], acc[mt][nt][3]);
            *reinterpret_cast<__half2*>(&Out[(size_t)r * VV + cn]) = h01;
            *reinterpret_cast<__half2*>(&Out[(size_t)(r + 8) * VV + cn]) = h23;
        }
    }
}

// ---------------------------------------------------------------------------
// Reductions (deterministic)
// ---------------------------------------------------------------------------
__device__ __forceinline__ float warpReduceSum(float v) {
#pragma unroll
    for (int o = 16; o > 0; o >>= 1) v += __shfl_xor_sync(0xffffffffu, v, o);
    return v;
}
__device__ __forceinline__ float warpReduceMax(float v) {
#pragma unroll
    for (int o = 16; o > 0; o >>= 1) v = fmaxf(v, __shfl_xor_sync(0xffffffffu, v, o));
    return v;
}
__device__ __forceinline__ float blockReduceSum(float v, float* sp) {
    v = warpReduceSum(v);
    __syncthreads();
    if ((threadIdx.x & 31) == 0) sp[threadIdx.x >> 5] = v;
    __syncthreads();
    float r = sp[0];
#pragma unroll
    for (int i = 1; i < 8; ++i) r += sp[i];
    return r;
}
__device__ __forceinline__ float blockReduceMax(float v, float* sp) {
    v = warpReduceMax(v);
    __syncthreads();
    if ((threadIdx.x & 31) == 0) sp[threadIdx.x >> 5] = v;
    __syncthreads();
    float r = sp[0];
#pragma unroll
    for (int i = 1; i < 8; ++i) r = fmaxf(r, sp[i]);
    return r;
}

// ---------------------------------------------------------------------------
// Per-row JSD (beta = 0.5, T = 1), 2 passes on fp16 logits
// ---------------------------------------------------------------------------
__global__ __launch_bounds__(256) void jsd_kernel() {
    __shared__ float sp[8];
    const int row = blockIdx.x;
    const int tid = threadIdx.x;
    const __half2* s2 = reinterpret_cast<const __half2*>(g_logits_s + (size_t)row * VV);
    const __half2* t2 = reinterpret_cast<const __half2*>(g_logits_t + (size_t)row * VV);
    const int NV2 = VV / 2;   // 16000

    float ms = -1e30f, ss = 0.0f, mt = -1e30f, st = 0.0f;
    for (int j = tid; j < NV2; j += 256) {
        const float2 vs = __half22float2(s2[j]);
        const float2 vt = __half22float2(t2[j]);
        {
            const float v = fmaxf(vs.x, vs.y);
            if (v > ms) { ss = ss * __expf(ms - v); ms = v; }
            ss += __expf(vs.x - ms) + __expf(vs.y - ms);
        }
        {
            const float v = fmaxf(vt.x, vt.y);
            if (v > mt) { st = st * __expf(mt - v); mt = v; }
            st += __expf(vt.x - mt) + __expf(vt.y - mt);
        }
    }
    const float Ms = blockReduceMax(ms, sp);
    const float Mt = blockReduceMax(mt, sp);
    ss *= __expf(ms - Ms);
    st *= __expf(mt - Mt);
    const float Ss = blockReduceSum(ss, sp);
    const float St = blockReduceSum(st, sp);
    const float lse_s = Ms + __logf(Ss);
    const float lse_t = Mt + __logf(St);

    float acc = 0.0f;
    for (int j = tid; j < NV2; j += 256) {
        const float2 vs = __half22float2(s2[j]);
        const float2 vt = __half22float2(t2[j]);
#pragma unroll
        for (int c = 0; c < 2; ++c) {
            const float lq = (c ? vs.y : vs.x) - lse_s;
            const float lp = (c ? vt.y : vt.x) - lse_t;
            const float q = __expf(lq);
            const float p = __expf(lp);
            const float m = 0.5f * (p + q);
            const float lm = __logf(fmaxf(m, 1e-30f));
            acc += 0.5f * (p * (lp - lm) + q * (lq - lm));
        }
    }
    acc = blockReduceSum(acc, sp);
    if (tid == 0) g_rowloss[row] = acc;
}

__global__ __launch_bounds__(256) void finalize_kernel(float* out) {
    __shared__ float sp[8];
    float v = 0.0f;
    for (int i = threadIdx.x; i < BT; i += 256) v += g_rowloss[i];
    v = blockReduceSum(v, sp);
    if (threadIdx.x == 0) out[0] = v * (1.0f / (float)BT);
}

// ---------------------------------------------------------------------------
// Launch
// ---------------------------------------------------------------------------
extern "C" void kernel_launch(void* const* d_in, const int* in_sizes, int n_in,
                              void* d_out, int out_size) {
    const float* xs = (const float*)d_in[0];
    const float* xt = (const float*)d_in[1];
    const float* ws = (const float*)d_in[2];
    const float* wt = (const float*)d_in[3];

    conv_kernel<<<dim3((BT * HD) / (256 * 8), 2), 256>>>(xs, xt, 0);
    conv_kernel<<<dim3((VV * HD) / (256 * 8), 2), 256>>>(ws, wt, 1);

    cudaFuncSetAttribute(gemm_bf16_kernel,
                         cudaFuncAttributeMaxDynamicSharedMemorySize, SMEM_TOTAL);
    gemm_bf16_kernel<<<dim3(M_TILES * N_TILES, 1, 2), 256, SMEM_TOTAL>>>();

    jsd_kernel<<<BT, 256>>>();
    finalize_kernel<<<1, 256>>>((float*)d_out);
}

// round 6
// speedup vs baseline: 4.1270x; 1.0497x over previous
#include <cuda_runtime.h>
#include <cuda_bf16.h>
#include <cuda_fp16.h>
#include <cstdint>
#include <math.h>

#define BT 4096
#define HD 2048
#define VV 32000

#define BM 128
#define BN 128
#define BK 64                       // bf16 elements per k-stage
#define STAGES 3
#define NITER (HD / BK)             // 32
#define A_BYTES (BM * 128)          // 16 KB
#define B_BYTES (BN * 128)          // 16 KB
#define STAGE_BYTES (A_BYTES + B_BYTES)
#define SMEM_TOTAL (STAGES * STAGE_BYTES)   // 96 KB -> 2 CTAs/SM

#define M_TILES (BT / BM)           // 32
#define N_TILES (VV / BN)           // 250

// ---------------------------------------------------------------------------
// Scratch (static __device__; referenced ONLY from device code)
// ---------------------------------------------------------------------------
__device__ __half g_logits_s[(size_t)BT * VV];   // 256 MB
__device__ __half g_logits_t[(size_t)BT * VV];   // 256 MB
__device__ float g_rowloss[BT];
__device__ __align__(16) __nv_bfloat16 g_Xb[(size_t)2 * BT * HD];   // 33.5 MB
__device__ __align__(16) __nv_bfloat16 g_Wb[(size_t)2 * VV * HD];   // 262 MB

// ---------------------------------------------------------------------------
// PTX helpers (baseline ISA only: cp.async, ldmatrix, mma.sync)
// ---------------------------------------------------------------------------
__device__ __forceinline__ uint32_t smem_u32(const void* p) {
    uint32_t a;
    asm("{ .reg .u64 t; cvta.to.shared.u64 t, %1; cvt.u32.u64 %0, t; }" : "=r"(a) : "l"(p));
    return a;
}

#define CP_ASYNC16(dst, src) \
    asm volatile("cp.async.cg.shared.global [%0], [%1], 16;" :: "r"(dst), "l"(src))
#define CP_COMMIT() asm volatile("cp.async.commit_group;" ::: "memory")
#define CP_WAIT(n)  asm volatile("cp.async.wait_group %0;" :: "n"(n) : "memory")

__device__ __forceinline__ void ldsm_x4(uint32_t& r0, uint32_t& r1, uint32_t& r2, uint32_t& r3,
                                        uint32_t addr) {
    asm volatile("ldmatrix.sync.aligned.m8n8.x4.shared.b16 {%0,%1,%2,%3}, [%4];"
                 : "=r"(r0), "=r"(r1), "=r"(r2), "=r"(r3) : "r"(addr));
}

__device__ __forceinline__ void mma_bf16(float c[4], const uint32_t a[4], const uint32_t b[2]) {
    asm volatile(
        "mma.sync.aligned.m16n8k16.row.col.f32.bf16.bf16.f32 "
        "{%0,%1,%2,%3}, {%4,%5,%6,%7}, {%8,%9}, {%0,%1,%2,%3};\n"
        : "+f"(c[0]), "+f"(c[1]), "+f"(c[2]), "+f"(c[3])
        : "r"(a[0]), "r"(a[1]), "r"(a[2]), "r"(a[3]), "r"(b[0]), "r"(b[1]));
}

// SW128 swizzle inside a row-major (row x 128 B) tile; kc16 in 0..7
__device__ __forceinline__ uint32_t tile_off(int row, int kc) {
    return (uint32_t)(row * 128 + ((kc ^ (row & 7)) << 4));
}

// ---------------------------------------------------------------------------
// fp32 -> bf16 conversion. dst chosen inside device code.
// ---------------------------------------------------------------------------
__device__ __forceinline__ uint32_t pack2bf(float a, float b) {
    __nv_bfloat162 h = __floats2bfloat162_rn(a, b);
    return *reinterpret_cast<uint32_t*>(&h);
}

__global__ __launch_bounds__(256) void conv_kernel(const float* __restrict__ src0,
                                                   const float* __restrict__ src1,
                                                   int isW) {
    const size_t n_per_model = isW ? (size_t)VV * HD : (size_t)BT * HD;
    __nv_bfloat16* dst = (isW ? g_Wb : g_Xb) + blockIdx.y * n_per_model;
    const float* src = blockIdx.y ? src1 : src0;
    const size_t idx = ((size_t)blockIdx.x * 256 + threadIdx.x) * 8;
    float4 f0 = *reinterpret_cast<const float4*>(src + idx);
    float4 f1 = *reinterpret_cast<const float4*>(src + idx + 4);
    uint4 u;
    u.x = pack2bf(f0.x, f0.y);  u.y = pack2bf(f0.z, f0.w);
    u.z = pack2bf(f1.x, f1.y);  u.w = pack2bf(f1.z, f1.w);
    *reinterpret_cast<uint4*>(dst + idx) = u;
}

// ---------------------------------------------------------------------------
// GEMM: logits[m, n] = sum_k Xb[m, k] * Wb[n, k]  -> fp16 logits
// CTA tile 128x128, 4 warps in 2(M) x 2(N), warp tile 64x64 (m16n8k16)
// 96 KB smem -> 2 CTAs/SM. grid.x m-fastest for W reuse in L2; grid.z = model
// ---------------------------------------------------------------------------
__global__ __launch_bounds__(128, 2) void gemm_bf16_kernel() {
    extern __shared__ __align__(1024) uint8_t smem[];
    const uint32_t sbase = smem_u32(smem);

    const int bid = blockIdx.x;
    const int m0 = (bid & 31) << 7;       // 32 m-tiles fastest
    const int n0 = (bid >> 5) << 7;       // 250 n-tiles of 128
    const int model = blockIdx.z;

    const __nv_bfloat16* X = g_Xb + (size_t)model * BT * HD;
    const __nv_bfloat16* W = g_Wb + (size_t)model * VV * HD;
    __half* Out = model ? g_logits_t : g_logits_s;

    const int tid = threadIdx.x;
    const int lane = tid & 31;
    const int warp = tid >> 5;
    const int warpM = (warp & 1) * 64;
    const int warpN = (warp >> 1) * 64;

    // cp.async mapping: 128 threads; per tile 1024 16-B chunks -> 8 per thread
    const int ld_row = tid >> 3;          // 0..15, stride 16 over 8 iters
    const int ld_kc = tid & 7;

    float acc[4][8][4];
#pragma unroll
    for (int mt = 0; mt < 4; ++mt)
#pragma unroll
        for (int nt = 0; nt < 8; ++nt)
#pragma unroll
            for (int i = 0; i < 4; ++i) acc[mt][nt][i] = 0.0f;

    auto load_stage = [&](int it) {
        const int slot = it % STAGES;
        const uint32_t sA = sbase + slot * STAGE_BYTES;
        const uint32_t sB = sA + A_BYTES;
        const int kt = it * BK;
#pragma unroll
        for (int i = 0; i < 8; ++i) {
            const int row = ld_row + i * 16;
            CP_ASYNC16(sA + tile_off(row, ld_kc), X + (size_t)(m0 + row) * HD + kt + ld_kc * 8);
            CP_ASYNC16(sB + tile_off(row, ld_kc), W + (size_t)(n0 + row) * HD + kt + ld_kc * 8);
        }
        CP_COMMIT();
    };

    load_stage(0);
    load_stage(1);

    // ldmatrix per-lane address components
    const int a_r = lane & 15;                            // A: row within 16
    const int a_k = lane >> 4;                            // A: k-chunk select
    const int b_n = (lane & 7) + ((lane >> 4) & 1) * 8;   // B: n-row within 16
    const int b_k = (lane >> 3) & 1;                      // B: k-chunk select

    for (int it = 0; it < NITER; ++it) {
        CP_WAIT(1);
        __syncthreads();
        if (it + 2 < NITER) load_stage(it + 2);
        else CP_COMMIT();   // empty group keeps CP_WAIT(1) draining the real tail

        const int slot = it % STAGES;
        const uint32_t sA = sbase + slot * STAGE_BYTES;
        const uint32_t sB = sA + A_BYTES;

#pragma unroll
        for (int ks = 0; ks < 4; ++ks) {
            uint32_t a[4][4];
            uint32_t b[8][2];
#pragma unroll
            for (int mt = 0; mt < 4; ++mt) {
                const int row = warpM + mt * 16 + a_r;
                ldsm_x4(a[mt][0], a[mt][1], a[mt][2], a[mt][3],
                        sA + tile_off(row, ks * 2 + a_k));
            }
#pragma unroll
            for (int nh = 0; nh < 4; ++nh) {
                const int row = warpN + nh * 16 + b_n;
                uint32_t r0, r1, r2, r3;
                ldsm_x4(r0, r1, r2, r3, sB + tile_off(row, ks * 2 + b_k));
                b[nh * 2 + 0][0] = r0;  b[nh * 2 + 0][1] = r1;
                b[nh * 2 + 1][0] = r2;  b[nh * 2 + 1][1] = r3;
            }
#pragma unroll
            for (int mt = 0; mt < 4; ++mt)
#pragma unroll
                for (int nt = 0; nt < 8; ++nt)
                    mma_bf16(acc[mt][nt], a[mt], b[nt]);
        }
    }

    const int g = lane >> 2;
    const int tig = lane & 3;
#pragma unroll
    for (int mt = 0; mt < 4; ++mt) {
#pragma unroll
        for (int nt = 0; nt < 8; ++nt) {
            const int r = m0 + warpM + mt * 16 + g;
            const int cn = n0 + warpN + nt * 8 + tig * 2;
            __half2 h01 = __floats2half2_rn(acc[mt][nt][0], acc[mt][nt][1]);
            __half2 h23 = __floats2half2_rn(acc[mt][nt][2], acc[mt][nt][3]);
            *reinterpret_cast<__half2*>(&Out[(size_t)r * VV + cn]) = h01;
            *reinterpret_cast<__half2*>(&Out[(size_t)(r + 8) * VV + cn]) = h23;
        }
    }
}

// ---------------------------------------------------------------------------
// Reductions (deterministic)
// ---------------------------------------------------------------------------
__device__ __forceinline__ float warpReduceSum(float v) {
#pragma unroll
    for (int o = 16; o > 0; o >>= 1) v += __shfl_xor_sync(0xffffffffu, v, o);
    return v;
}
__device__ __forceinline__ float warpReduceMax(float v) {
#pragma unroll
    for (int o = 16; o > 0; o >>= 1) v = fmaxf(v, __shfl_xor_sync(0xffffffffu, v, o));
    return v;
}
__device__ __forceinline__ float blockReduceSum(float v, float* sp) {
    v = warpReduceSum(v);
    __syncthreads();
    if ((threadIdx.x & 31) == 0) sp[threadIdx.x >> 5] = v;
    __syncthreads();
    float r = sp[0];
#pragma unroll
    for (int i = 1; i < 8; ++i) r += sp[i];
    return r;
}
__device__ __forceinline__ float blockReduceMax(float v, float* sp) {
    v = warpReduceMax(v);
    __syncthreads();
    if ((threadIdx.x & 31) == 0) sp[threadIdx.x >> 5] = v;
    __syncthreads();
    float r = sp[0];
#pragma unroll
    for (int i = 1; i < 8; ++i) r = fmaxf(r, sp[i]);
    return r;
}

// ---------------------------------------------------------------------------
// Per-row JSD (beta = 0.5, T = 1), 2 passes on fp16 logits
// ---------------------------------------------------------------------------
__global__ __launch_bounds__(256) void jsd_kernel() {
    __shared__ float sp[8];
    const int row = blockIdx.x;
    const int tid = threadIdx.x;
    const __half2* s2 = reinterpret_cast<const __half2*>(g_logits_s + (size_t)row * VV);
    const __half2* t2 = reinterpret_cast<const __half2*>(g_logits_t + (size_t)row * VV);
    const int NV2 = VV / 2;   // 16000

    float ms = -1e30f, ss = 0.0f, mt = -1e30f, st = 0.0f;
    for (int j = tid; j < NV2; j += 256) {
        const float2 vs = __half22float2(s2[j]);
        const float2 vt = __half22float2(t2[j]);
        {
            const float v = fmaxf(vs.x, vs.y);
            if (v > ms) { ss = ss * __expf(ms - v); ms = v; }
            ss += __expf(vs.x - ms) + __expf(vs.y - ms);
        }
        {
            const float v = fmaxf(vt.x, vt.y);
            if (v > mt) { st = st * __expf(mt - v); mt = v; }
            st += __expf(vt.x - mt) + __expf(vt.y - mt);
        }
    }
    const float Ms = blockReduceMax(ms, sp);
    const float Mt = blockReduceMax(mt, sp);
    ss *= __expf(ms - Ms);
    st *= __expf(mt - Mt);
    const float Ss = blockReduceSum(ss, sp);
    const float St = blockReduceSum(st, sp);
    const float lse_s = Ms + __logf(Ss);
    const float lse_t = Mt + __logf(St);

    float acc = 0.0f;
    for (int j = tid; j < NV2; j += 256) {
        const float2 vs = __half22float2(s2[j]);
        const float2 vt = __half22float2(t2[j]);
#pragma unroll
        for (int c = 0; c < 2; ++c) {
            const float lq = (c ? vs.y : vs.x) - lse_s;
            const float lp = (c ? vt.y : vt.x) - lse_t;
            const float q = __expf(lq);
            const float p = __expf(lp);
            const float m = 0.5f * (p + q);
            const float lm = __logf(fmaxf(m, 1e-30f));
            acc += 0.5f * (p * (lp - lm) + q * (lq - lm));
        }
    }
    acc = blockReduceSum(acc, sp);
    if (tid == 0) g_rowloss[row] = acc;
}

__global__ __launch_bounds__(256) void finalize_kernel(float* out) {
    __shared__ float sp[8];
    float v = 0.0f;
    for (int i = threadIdx.x; i < BT; i += 256) v += g_rowloss[i];
    v = blockReduceSum(v, sp);
    if (threadIdx.x == 0) out[0] = v * (1.0f / (float)BT);
}

// ---------------------------------------------------------------------------
// Launch
// ---------------------------------------------------------------------------
extern "C" void kernel_launch(void* const* d_in, const int* in_sizes, int n_in,
                              void* d_out, int out_size) {
    const float* xs = (const float*)d_in[0];
    const float* xt = (const float*)d_in[1];
    const float* ws = (const float*)d_in[2];
    const float* wt = (const float*)d_in[3];

    conv_kernel<<<dim3((BT * HD) / (256 * 8), 2), 256>>>(xs, xt, 0);
    conv_kernel<<<dim3((VV * HD) / (256 * 8), 2), 256>>>(ws, wt, 1);

    cudaFuncSetAttribute(gemm_bf16_kernel,
                         cudaFuncAttributeMaxDynamicSharedMemorySize, SMEM_TOTAL);
    gemm_bf16_kernel<<<dim3(M_TILES * N_TILES, 1, 2), 128, SMEM_TOTAL>>>();

    jsd_kernel<<<BT, 256>>>();
    finalize_kernel<<<1, 256>>>((float*)d_out);
}